// round 1
// baseline (speedup 1.0000x reference)
#include <cuda_runtime.h>
#include <cuda_bf16.h>
#include <math_constants.h>

// Problem constants
#define B_DIM 4
#define T_DIM 2048
#define C_DIM 1024
#define H_DIM 16
#define D_DIM 64
#define M_ROWS (B_DIM * T_DIM)   // 8192

// Scratch (allocation-free rule: __device__ globals)
__device__ float g_qkv[(size_t)B_DIM * T_DIM * 3 * C_DIM];  // (B,T,3C) ~100MB
__device__ float g_att[(size_t)B_DIM * T_DIM * C_DIM];      // (B,T,C)  ~33MB

// ---------------------------------------------------------------------------
// SGEMM: C[M,N] = A[M,K] @ B[K,N] + bias[N]
// 128x128 block tile, BK=8, 256 threads, 8x8 per-thread micro-tile.
// ---------------------------------------------------------------------------
#define BM 128
#define BN 128
#define BK 8

__global__ __launch_bounds__(256) void sgemm_bias_kernel(
    const float* __restrict__ A, const float* __restrict__ Bmat,
    const float* __restrict__ bias, float* __restrict__ C,
    int M, int N, int K)
{
    __shared__ float As[BK][BM + 4];   // +4 pad: kills 2-way store conflicts, keeps 16B align
    __shared__ float Bs[BK][BN];

    const int tid = threadIdx.x;
    const int m0 = blockIdx.y * BM;
    const int n0 = blockIdx.x * BN;

    // A-tile loader: 128 rows x 8 cols; each thread one float4 along K
    const int a_row = tid >> 1;            // 0..127
    const int a_col = (tid & 1) * 4;       // 0 or 4
    // B-tile loader: 8 rows x 128 cols; each thread one float4 along N
    const int b_row = tid >> 5;            // 0..7
    const int b_col = (tid & 31) * 4;      // 0..124

    // micro-tile coordinates
    const int tm = (tid >> 4) * 8;         // 0..120
    const int tn = (tid & 15) * 8;         // 0..120

    float acc[8][8];
    #pragma unroll
    for (int i = 0; i < 8; ++i)
        #pragma unroll
        for (int j = 0; j < 8; ++j) acc[i][j] = 0.0f;

    const float* Aptr = A + (size_t)(m0 + a_row) * K + a_col;
    const float* Bptr = Bmat + (size_t)b_row * N + n0 + b_col;

    for (int k0 = 0; k0 < K; k0 += BK) {
        float4 av = *(const float4*)(Aptr + k0);
        float4 bv = *(const float4*)(Bptr + (size_t)k0 * N);
        As[a_col + 0][a_row] = av.x;
        As[a_col + 1][a_row] = av.y;
        As[a_col + 2][a_row] = av.z;
        As[a_col + 3][a_row] = av.w;
        *(float4*)&Bs[b_row][b_col] = bv;
        __syncthreads();

        #pragma unroll
        for (int kk = 0; kk < BK; ++kk) {
            float a_frag[8], b_frag[8];
            float4 a0 = *(const float4*)&As[kk][tm];
            float4 a1 = *(const float4*)&As[kk][tm + 4];
            float4 b0 = *(const float4*)&Bs[kk][tn];
            float4 b1 = *(const float4*)&Bs[kk][tn + 4];
            a_frag[0]=a0.x; a_frag[1]=a0.y; a_frag[2]=a0.z; a_frag[3]=a0.w;
            a_frag[4]=a1.x; a_frag[5]=a1.y; a_frag[6]=a1.z; a_frag[7]=a1.w;
            b_frag[0]=b0.x; b_frag[1]=b0.y; b_frag[2]=b0.z; b_frag[3]=b0.w;
            b_frag[4]=b1.x; b_frag[5]=b1.y; b_frag[6]=b1.z; b_frag[7]=b1.w;
            #pragma unroll
            for (int i = 0; i < 8; ++i)
                #pragma unroll
                for (int j = 0; j < 8; ++j)
                    acc[i][j] = fmaf(a_frag[i], b_frag[j], acc[i][j]);
        }
        __syncthreads();
    }

    // epilogue: add bias, store
    float bvals[8];
    #pragma unroll
    for (int j = 0; j < 8; ++j) bvals[j] = bias[n0 + tn + j];

    #pragma unroll
    for (int i = 0; i < 8; ++i) {
        float* crow = C + (size_t)(m0 + tm + i) * N + n0 + tn;
        float4 o0, o1;
        o0.x = acc[i][0] + bvals[0];
        o0.y = acc[i][1] + bvals[1];
        o0.z = acc[i][2] + bvals[2];
        o0.w = acc[i][3] + bvals[3];
        o1.x = acc[i][4] + bvals[4];
        o1.y = acc[i][5] + bvals[5];
        o1.z = acc[i][6] + bvals[6];
        o1.w = acc[i][7] + bvals[7];
        *(float4*)(crow)     = o0;
        *(float4*)(crow + 4) = o1;
    }
}

// ---------------------------------------------------------------------------
// Causal flash attention, fp32 SIMT.
// grid: (B*H, T/AT_ROWS), block: AT_ROWS threads (one q-row per thread).
// q and o accumulator live in registers (64+64). K/V tiles staged in smem;
// score tile staged in smem so the online-softmax rescale is once per tile.
// ---------------------------------------------------------------------------
#define AT_ROWS 128
#define AT_BC   32

__global__ __launch_bounds__(AT_ROWS) void flash_attn_kernel(
    const float* __restrict__ qkv, float* __restrict__ out)
{
    __shared__ float Ks[AT_BC][D_DIM];
    __shared__ float Vs[AT_BC][D_DIM];
    __shared__ float Ss[AT_BC][AT_ROWS];

    const int tid = threadIdx.x;
    const int b = blockIdx.x >> 4;        // H_DIM = 16
    const int h = blockIdx.x & (H_DIM - 1);
    const int q_idx = blockIdx.y * AT_ROWS + tid;

    const size_t row_stride = 3 * C_DIM;
    const float* qptr = qkv + ((size_t)b * T_DIM + q_idx) * row_stride + h * D_DIM;

    // q scaled by 1/sqrt(D) up front
    float q[D_DIM];
    #pragma unroll
    for (int d = 0; d < D_DIM; d += 4) {
        float4 v = *(const float4*)(qptr + d);
        q[d]     = v.x * 0.125f;
        q[d + 1] = v.y * 0.125f;
        q[d + 2] = v.z * 0.125f;
        q[d + 3] = v.w * 0.125f;
    }
    float o[D_DIM];
    #pragma unroll
    for (int d = 0; d < D_DIM; ++d) o[d] = 0.0f;
    float m = -CUDART_INF_F;
    float l = 0.0f;

    const float* kbase = qkv + (size_t)b * T_DIM * row_stride + C_DIM + (size_t)h * D_DIM;
    const float* vbase = kbase + C_DIM;

    const int ntiles = (blockIdx.y + 1) * (AT_ROWS / AT_BC);  // causal: only tiles up to block max

    for (int t = 0; t < ntiles; ++t) {
        const int k0 = t * AT_BC;
        __syncthreads();
        // load K/V tile: 32 rows x 64 cols each = 512 float4 each; 4 per thread
        #pragma unroll
        for (int i = 0; i < 4; ++i) {
            int idx = tid + i * AT_ROWS;      // 0..511
            int r = idx >> 4;                 // 16 float4 per row
            int c = (idx & 15) * 4;
            const size_t off = (size_t)(k0 + r) * row_stride + c;
            *(float4*)&Ks[r][c] = *(const float4*)(kbase + off);
            *(float4*)&Vs[r][c] = *(const float4*)(vbase + off);
        }
        __syncthreads();

        // pass 1: scores + tile max
        float mt = m;
        #pragma unroll 4
        for (int kk = 0; kk < AT_BC; ++kk) {
            float s = -CUDART_INF_F;
            if (k0 + kk <= q_idx) {
                s = 0.0f;
                const float4* kr = (const float4*)Ks[kk];
                #pragma unroll
                for (int d4 = 0; d4 < 16; ++d4) {
                    float4 kv = kr[d4];
                    s = fmaf(q[4 * d4],     kv.x, s);
                    s = fmaf(q[4 * d4 + 1], kv.y, s);
                    s = fmaf(q[4 * d4 + 2], kv.z, s);
                    s = fmaf(q[4 * d4 + 3], kv.w, s);
                }
            }
            Ss[kk][tid] = s;
            mt = fmaxf(mt, s);
        }

        // rescale previous accumulator once per tile
        float corr = __expf(m - mt);           // m=-inf on first tile -> corr=0, o already 0
        l *= corr;
        #pragma unroll
        for (int d = 0; d < D_DIM; ++d) o[d] *= corr;

        // pass 2: probs + PV accumulate
        #pragma unroll 2
        for (int kk = 0; kk < AT_BC; ++kk) {
            float p = __expf(Ss[kk][tid] - mt);   // masked s=-inf -> p=0
            l += p;
            const float4* vr = (const float4*)Vs[kk];
            #pragma unroll
            for (int d4 = 0; d4 < 16; ++d4) {
                float4 vv = vr[d4];
                o[4 * d4]     = fmaf(p, vv.x, o[4 * d4]);
                o[4 * d4 + 1] = fmaf(p, vv.y, o[4 * d4 + 1]);
                o[4 * d4 + 2] = fmaf(p, vv.z, o[4 * d4 + 2]);
                o[4 * d4 + 3] = fmaf(p, vv.w, o[4 * d4 + 3]);
            }
        }
        m = mt;
    }

    const float inv_l = 1.0f / l;
    float* optr = out + ((size_t)b * T_DIM + q_idx) * C_DIM + h * D_DIM;
    #pragma unroll
    for (int d = 0; d < D_DIM; d += 4) {
        float4 v;
        v.x = o[d] * inv_l;
        v.y = o[d + 1] * inv_l;
        v.z = o[d + 2] * inv_l;
        v.w = o[d + 3] * inv_l;
        *(float4*)(optr + d) = v;
    }
}

// ---------------------------------------------------------------------------
// Launch
// ---------------------------------------------------------------------------
extern "C" void kernel_launch(void* const* d_in, const int* in_sizes, int n_in,
                              void* d_out, int out_size)
{
    const float* x      = (const float*)d_in[0];
    const float* w_attn = (const float*)d_in[1];
    const float* b_attn = (const float*)d_in[2];
    const float* w_proj = (const float*)d_in[3];
    const float* b_proj = (const float*)d_in[4];
    float* out = (float*)d_out;

    void* qkv_ptr = nullptr;
    void* att_ptr = nullptr;
    cudaGetSymbolAddress(&qkv_ptr, g_qkv);
    cudaGetSymbolAddress(&att_ptr, g_att);
    float* qkv = (float*)qkv_ptr;
    float* att = (float*)att_ptr;

    // 1) qkv = x @ w_attn + b_attn           (8192 x 3072 x 1024)
    {
        dim3 grid((3 * C_DIM) / BN, M_ROWS / BM);
        sgemm_bias_kernel<<<grid, 256>>>(x, w_attn, b_attn, qkv,
                                         M_ROWS, 3 * C_DIM, C_DIM);
    }
    // 2) causal MHA -> att (B,T,C)
    {
        dim3 grid(B_DIM * H_DIM, T_DIM / AT_ROWS);
        flash_attn_kernel<<<grid, AT_ROWS>>>(qkv, att);
    }
    // 3) out = att @ w_proj + b_proj         (8192 x 1024 x 1024)
    {
        dim3 grid(C_DIM / BN, M_ROWS / BM);
        sgemm_bias_kernel<<<grid, 256>>>(att, w_proj, b_proj, out,
                                         M_ROWS, C_DIM, C_DIM);
    }
}

// round 3
// speedup vs baseline: 1.3975x; 1.3975x over previous
#include <cuda_runtime.h>
#include <cuda_bf16.h>
#include <math_constants.h>
#include <cstdint>

// ---------------------------------------------------------------------------
// Problem constants
// ---------------------------------------------------------------------------
#define B_DIM 4
#define T_DIM 2048
#define C_DIM 1024
#define H_DIM 16
#define D_DIM 64
#define M_ROWS (B_DIM * T_DIM)       // 8192
#define N_QKV  (3 * C_DIM)           // 3072

// ---------------------------------------------------------------------------
// Device scratch (allocation-free rule)
// ---------------------------------------------------------------------------
__device__ float g_qkv[(size_t)M_ROWS * N_QKV];
__device__ float g_att[(size_t)M_ROWS * C_DIM];
__device__ __nv_bfloat16 g_xh[(size_t)M_ROWS * C_DIM];
__device__ __nv_bfloat16 g_xl[(size_t)M_ROWS * C_DIM];
__device__ __nv_bfloat16 g_wth[(size_t)N_QKV * C_DIM];   // w_attn^T [3072][1024]
__device__ __nv_bfloat16 g_wtl[(size_t)N_QKV * C_DIM];
__device__ __nv_bfloat16 g_wpth[(size_t)C_DIM * C_DIM];  // w_proj^T [1024][1024]
__device__ __nv_bfloat16 g_wptl[(size_t)C_DIM * C_DIM];
__device__ __nv_bfloat16 g_ath[(size_t)M_ROWS * C_DIM];
__device__ __nv_bfloat16 g_atl[(size_t)M_ROWS * C_DIM];

// ---------------------------------------------------------------------------
// Helpers
// ---------------------------------------------------------------------------
__device__ __forceinline__ uint32_t smem_u32(const void* p) {
    uint32_t a;
    asm("{ .reg .u64 t; cvta.to.shared.u64 t, %1; cvt.u32.u64 %0, t; }"
        : "=r"(a) : "l"(p));
    return a;
}

__device__ __forceinline__ void cp16(uint32_t dst, const void* src) {
    asm volatile("cp.async.cg.shared.global [%0], [%1], 16;"
                 :: "r"(dst), "l"(src));
}
#define CP_COMMIT() asm volatile("cp.async.commit_group;" ::: "memory")
#define CP_WAIT(n)  asm volatile("cp.async.wait_group %0;" :: "n"(n) : "memory")

__device__ __forceinline__ void ldsm4(uint32_t* r, uint32_t addr) {
    asm volatile("ldmatrix.sync.aligned.m8n8.x4.shared.b16 {%0,%1,%2,%3}, [%4];"
                 : "=r"(r[0]), "=r"(r[1]), "=r"(r[2]), "=r"(r[3]) : "r"(addr));
}

__device__ __forceinline__ void mma16816(float* c, const uint32_t* a,
                                         const uint32_t* b) {
    asm volatile(
        "mma.sync.aligned.m16n8k16.row.col.f32.bf16.bf16.f32 "
        "{%0,%1,%2,%3}, {%4,%5,%6,%7}, {%8,%9}, {%0,%1,%2,%3};"
        : "+f"(c[0]), "+f"(c[1]), "+f"(c[2]), "+f"(c[3])
        : "r"(a[0]), "r"(a[1]), "r"(a[2]), "r"(a[3]), "r"(b[0]), "r"(b[1]));
}

// Fast exp on the FMA pipe (no MUFU). Valid for x <= 0; err ~3e-6 rel.
__device__ __forceinline__ float fexp(float x) {
    const float LOG2E = 1.4426950408889634f;
    const float MAGIC = 12582912.0f;          // 1.5 * 2^23
    x = fmaxf(x, -80.0f);
    float t = fmaf(x, LOG2E, MAGIC);
    int   i = __float_as_int(t);
    float n = t - MAGIC;
    float f = fmaf(x, LOG2E, -n);             // f in [-0.5, 0.5]
    float p = 0.0013333558f;
    p = fmaf(p, f, 0.0096181291f);
    p = fmaf(p, f, 0.0555041086f);
    p = fmaf(p, f, 0.2402265069f);
    p = fmaf(p, f, 0.6931471806f);
    p = fmaf(p, f, 1.0f);
    return __int_as_float(__float_as_int(p) + (i << 23));
}

// ---------------------------------------------------------------------------
// Prep kernels: fp32 -> bf16 hi/lo split (+ transposed variant for weights)
// ---------------------------------------------------------------------------
__global__ void k_split(const float* __restrict__ in,
                        __nv_bfloat16* __restrict__ hi,
                        __nv_bfloat16* __restrict__ lo, int n)
{
    int i = (blockIdx.x * blockDim.x + threadIdx.x) * 4;
    if (i >= n) return;
    float4 v = *(const float4*)(in + i);
    float f[4] = {v.x, v.y, v.z, v.w};
    __nv_bfloat16 h[4], l[4];
#pragma unroll
    for (int j = 0; j < 4; ++j) {
        h[j] = __float2bfloat16(f[j]);
        l[j] = __float2bfloat16(f[j] - __bfloat162float(h[j]));
    }
    *(__nv_bfloat162*)(hi + i)     = __nv_bfloat162(h[0], h[1]);
    *(__nv_bfloat162*)(hi + i + 2) = __nv_bfloat162(h[2], h[3]);
    *(__nv_bfloat162*)(lo + i)     = __nv_bfloat162(l[0], l[1]);
    *(__nv_bfloat162*)(lo + i + 2) = __nv_bfloat162(l[2], l[3]);
}

// W[K][N] row-major -> T[N][K] bf16 hi/lo
__global__ void k_transpose_split(const float* __restrict__ W,
                                  __nv_bfloat16* __restrict__ Th,
                                  __nv_bfloat16* __restrict__ Tl,
                                  int K, int N)
{
    __shared__ float tile[32][33];
    const int k0 = blockIdx.y * 32;
    const int n0 = blockIdx.x * 32;
    const int tx = threadIdx.x;
    const int ty = threadIdx.y;
#pragma unroll
    for (int r = 0; r < 4; ++r)
        tile[ty + r * 8][tx] = W[(size_t)(k0 + ty + r * 8) * N + n0 + tx];
    __syncthreads();
#pragma unroll
    for (int r = 0; r < 4; ++r) {
        float v = tile[tx][ty + r * 8];
        __nv_bfloat16 h = __float2bfloat16(v);
        __nv_bfloat16 l = __float2bfloat16(v - __bfloat162float(h));
        size_t o = (size_t)(n0 + ty + r * 8) * K + k0 + tx;
        Th[o] = h;
        Tl[o] = l;
    }
}

// ---------------------------------------------------------------------------
// HMMA GEMM: C[M][N] = A[M][K] @ Bt[N][K]^T + bias, bf16 hi/lo 3-product split.
// 128x128 CTA tile, BK=32, 8 warps (64x32 each), cp.async double buffer.
// ---------------------------------------------------------------------------
#define BK 32
#define LDSS 40                      // smem row stride in bf16 elements
#define TILE_B (128 * LDSS * 2)      // 10240 bytes per operand tile
#define STAGE_B (4 * TILE_B)         // Ah, Al, Bh, Bl
#define GEMM_SMEM (2 * STAGE_B)      // 81920 bytes

__global__ void __launch_bounds__(256, 1)
gemm_mma(const __nv_bfloat16* __restrict__ Ah, const __nv_bfloat16* __restrict__ Al,
         const __nv_bfloat16* __restrict__ Bh, const __nv_bfloat16* __restrict__ Bl,
         const float* __restrict__ bias, float* __restrict__ C, int N, int K)
{
    extern __shared__ __nv_bfloat16 sm[];
    const uint32_t sbase = smem_u32(sm);

    const int tid  = threadIdx.x;
    const int lane = tid & 31;
    const int wid  = tid >> 5;
    const int m0 = blockIdx.y * 128;
    const int n0 = blockIdx.x * 128;
    const int wm = (wid & 1) * 64;
    const int wn = (wid >> 1) * 32;

    float acc[4][4][4];
#pragma unroll
    for (int i = 0; i < 4; ++i)
#pragma unroll
        for (int j = 0; j < 4; ++j)
#pragma unroll
            for (int k = 0; k < 4; ++k) acc[i][j][k] = 0.0f;

    // loader: 512 16-byte slots per operand tile; 2 slots/thread/tile
    const int r0 = tid >> 2, s0 = (tid & 3);             // slot tid
    const int r1 = (tid + 256) >> 2, s1 = (tid & 3);     // slot tid+256

    const __nv_bfloat16* a0h = Ah + (size_t)(m0 + r0) * K + s0 * 8;
    const __nv_bfloat16* a0l = Al + (size_t)(m0 + r0) * K + s0 * 8;
    const __nv_bfloat16* b0h = Bh + (size_t)(n0 + r0) * K + s0 * 8;
    const __nv_bfloat16* b0l = Bl + (size_t)(n0 + r0) * K + s0 * 8;
    const __nv_bfloat16* a1h = Ah + (size_t)(m0 + r1) * K + s1 * 8;
    const __nv_bfloat16* a1l = Al + (size_t)(m0 + r1) * K + s1 * 8;
    const __nv_bfloat16* b1h = Bh + (size_t)(n0 + r1) * K + s1 * 8;
    const __nv_bfloat16* b1l = Bl + (size_t)(n0 + r1) * K + s1 * 8;
    const uint32_t d0 = (uint32_t)r0 * (LDSS * 2) + (uint32_t)s0 * 16;
    const uint32_t d1 = (uint32_t)r1 * (LDSS * 2) + (uint32_t)s1 * 16;

    auto load_chunk = [&](int c, int buf) {
        const int koff = c * BK;
        const uint32_t db = sbase + buf * STAGE_B;
        cp16(db + 0 * TILE_B + d0, a0h + koff);
        cp16(db + 1 * TILE_B + d0, a0l + koff);
        cp16(db + 2 * TILE_B + d0, b0h + koff);
        cp16(db + 3 * TILE_B + d0, b0l + koff);
        cp16(db + 0 * TILE_B + d1, a1h + koff);
        cp16(db + 1 * TILE_B + d1, a1l + koff);
        cp16(db + 2 * TILE_B + d1, b1h + koff);
        cp16(db + 3 * TILE_B + d1, b1l + koff);
        CP_COMMIT();
    };

    const int NC = K / BK;
    load_chunk(0, 0);

    for (int c = 0; c < NC; ++c) {
        const int buf = c & 1;
        if (c + 1 < NC) {
            load_chunk(c + 1, buf ^ 1);
            CP_WAIT(1);
        } else {
            CP_WAIT(0);
        }
        __syncthreads();

        const uint32_t tb = sbase + buf * STAGE_B;
#pragma unroll
        for (int ks = 0; ks < 2; ++ks) {
            uint32_t ah[4][4], al[4][4], bh[2][4], bl[2][4];
#pragma unroll
            for (int mi = 0; mi < 4; ++mi) {
                uint32_t off = (uint32_t)(wm + mi * 16 + (lane & 15)) * (LDSS * 2)
                             + ks * 32 + (lane >> 4) * 16;
                ldsm4(ah[mi], tb + 0 * TILE_B + off);
                ldsm4(al[mi], tb + 1 * TILE_B + off);
            }
#pragma unroll
            for (int np = 0; np < 2; ++np) {
                uint32_t off = (uint32_t)(wn + np * 16 + (lane & 7)
                             + ((lane >> 4) & 1) * 8) * (LDSS * 2)
                             + ks * 32 + ((lane >> 3) & 1) * 16;
                ldsm4(bh[np], tb + 2 * TILE_B + off);
                ldsm4(bl[np], tb + 3 * TILE_B + off);
            }
#pragma unroll
            for (int mi = 0; mi < 4; ++mi)
#pragma unroll
                for (int ni = 0; ni < 4; ++ni) {
                    const uint32_t* fh = &bh[ni >> 1][(ni & 1) * 2];
                    const uint32_t* fl = &bl[ni >> 1][(ni & 1) * 2];
                    mma16816(acc[mi][ni], ah[mi], fh);   // Ah*Bh
                    mma16816(acc[mi][ni], ah[mi], fl);   // Ah*Bl
                    mma16816(acc[mi][ni], al[mi], fh);   // Al*Bh
                }
        }
        __syncthreads();
    }

    // epilogue: bias + store
#pragma unroll
    for (int mi = 0; mi < 4; ++mi) {
        const int row = m0 + wm + mi * 16 + (lane >> 2);
#pragma unroll
        for (int ni = 0; ni < 4; ++ni) {
            const int col = n0 + wn + ni * 8 + (lane & 3) * 2;
            const float b0v = bias[col];
            const float b1v = bias[col + 1];
            float2 v0, v1;
            v0.x = acc[mi][ni][0] + b0v;
            v0.y = acc[mi][ni][1] + b1v;
            v1.x = acc[mi][ni][2] + b0v;
            v1.y = acc[mi][ni][3] + b1v;
            *(float2*)(C + (size_t)row * N + col)       = v0;
            *(float2*)(C + (size_t)(row + 8) * N + col) = v1;
        }
    }
}

// ---------------------------------------------------------------------------
// Causal flash attention, fp32 SIMT with FMA-pipe exp
// ---------------------------------------------------------------------------
#define AT_ROWS 128
#define AT_BC   32
#define NEG_BIG (-1e30f)

__global__ void __launch_bounds__(AT_ROWS) flash_attn_kernel(
    const float* __restrict__ qkv, float* __restrict__ out)
{
    __shared__ float Ks[AT_BC][D_DIM];
    __shared__ float Vs[AT_BC][D_DIM];
    __shared__ float Ss[AT_BC][AT_ROWS];

    const int tid = threadIdx.x;
    const int b = blockIdx.x >> 4;
    const int h = blockIdx.x & (H_DIM - 1);
    const int q_idx = blockIdx.y * AT_ROWS + tid;

    const size_t row_stride = 3 * C_DIM;
    const float* qptr = qkv + ((size_t)b * T_DIM + q_idx) * row_stride + h * D_DIM;

    float q[D_DIM];
#pragma unroll
    for (int d = 0; d < D_DIM; d += 4) {
        float4 v = *(const float4*)(qptr + d);
        q[d]     = v.x * 0.125f;
        q[d + 1] = v.y * 0.125f;
        q[d + 2] = v.z * 0.125f;
        q[d + 3] = v.w * 0.125f;
    }
    float o[D_DIM];
#pragma unroll
    for (int d = 0; d < D_DIM; ++d) o[d] = 0.0f;
    float m = NEG_BIG;
    float l = 0.0f;

    const float* kbase = qkv + (size_t)b * T_DIM * row_stride + C_DIM + (size_t)h * D_DIM;
    const float* vbase = kbase + C_DIM;

    const int ntiles = (blockIdx.y + 1) * (AT_ROWS / AT_BC);

    for (int t = 0; t < ntiles; ++t) {
        const int k0 = t * AT_BC;
        __syncthreads();
#pragma unroll
        for (int i = 0; i < 4; ++i) {
            int idx = tid + i * AT_ROWS;
            int r = idx >> 4;
            int c = (idx & 15) * 4;
            const size_t off = (size_t)(k0 + r) * row_stride + c;
            *(float4*)&Ks[r][c] = *(const float4*)(kbase + off);
            *(float4*)&Vs[r][c] = *(const float4*)(vbase + off);
        }
        __syncthreads();

        float mt = m;
#pragma unroll 4
        for (int kk = 0; kk < AT_BC; ++kk) {
            float s = NEG_BIG;
            if (k0 + kk <= q_idx) {
                s = 0.0f;
                const float4* kr = (const float4*)Ks[kk];
#pragma unroll
                for (int d4 = 0; d4 < 16; ++d4) {
                    float4 kv = kr[d4];
                    s = fmaf(q[4 * d4],     kv.x, s);
                    s = fmaf(q[4 * d4 + 1], kv.y, s);
                    s = fmaf(q[4 * d4 + 2], kv.z, s);
                    s = fmaf(q[4 * d4 + 3], kv.w, s);
                }
            }
            Ss[kk][tid] = s;
            mt = fmaxf(mt, s);
        }

        if (mt > m) {
            float corr = fexp(m - mt);
            l *= corr;
#pragma unroll
            for (int d = 0; d < D_DIM; ++d) o[d] *= corr;
        }

#pragma unroll 2
        for (int kk = 0; kk < AT_BC; ++kk) {
            float p = fexp(Ss[kk][tid] - mt);
            l += p;
            const float4* vr = (const float4*)Vs[kk];
#pragma unroll
            for (int d4 = 0; d4 < 16; ++d4) {
                float4 vv = vr[d4];
                o[4 * d4]     = fmaf(p, vv.x, o[4 * d4]);
                o[4 * d4 + 1] = fmaf(p, vv.y, o[4 * d4 + 1]);
                o[4 * d4 + 2] = fmaf(p, vv.z, o[4 * d4 + 2]);
                o[4 * d4 + 3] = fmaf(p, vv.w, o[4 * d4 + 3]);
            }
        }
        m = mt;
    }

    const float inv_l = 1.0f / l;
    float* optr = out + ((size_t)b * T_DIM + q_idx) * C_DIM + h * D_DIM;
#pragma unroll
    for (int d = 0; d < D_DIM; d += 4) {
        float4 v;
        v.x = o[d] * inv_l;
        v.y = o[d + 1] * inv_l;
        v.z = o[d + 2] * inv_l;
        v.w = o[d + 3] * inv_l;
        *(float4*)(optr + d) = v;
    }
}

// ---------------------------------------------------------------------------
// Launch
// ---------------------------------------------------------------------------
extern "C" void kernel_launch(void* const* d_in, const int* in_sizes, int n_in,
                              void* d_out, int out_size)
{
    const float* x      = (const float*)d_in[0];
    const float* w_attn = (const float*)d_in[1];
    const float* b_attn = (const float*)d_in[2];
    const float* w_proj = (const float*)d_in[3];
    const float* b_proj = (const float*)d_in[4];
    float* out = (float*)d_out;

    void *p_qkv, *p_att, *p_xh, *p_xl, *p_wth, *p_wtl, *p_wpth, *p_wptl, *p_ath, *p_atl;
    cudaGetSymbolAddress(&p_qkv,  g_qkv);
    cudaGetSymbolAddress(&p_att,  g_att);
    cudaGetSymbolAddress(&p_xh,   g_xh);
    cudaGetSymbolAddress(&p_xl,   g_xl);
    cudaGetSymbolAddress(&p_wth,  g_wth);
    cudaGetSymbolAddress(&p_wtl,  g_wtl);
    cudaGetSymbolAddress(&p_wpth, g_wpth);
    cudaGetSymbolAddress(&p_wptl, g_wptl);
    cudaGetSymbolAddress(&p_ath,  g_ath);
    cudaGetSymbolAddress(&p_atl,  g_atl);

    static bool attr_done = false;
    if (!attr_done) {
        cudaFuncSetAttribute(gemm_mma, cudaFuncAttributeMaxDynamicSharedMemorySize,
                             GEMM_SMEM);
        attr_done = true;
    }

    // 1) split x -> bf16 hi/lo
    {
        int n = M_ROWS * C_DIM;
        k_split<<<n / 4 / 256, 256>>>(x, (__nv_bfloat16*)p_xh, (__nv_bfloat16*)p_xl, n);
    }
    // 2) transpose + split weights
    {
        dim3 g(N_QKV / 32, C_DIM / 32);
        k_transpose_split<<<g, dim3(32, 8)>>>(w_attn, (__nv_bfloat16*)p_wth,
                                              (__nv_bfloat16*)p_wtl, C_DIM, N_QKV);
    }
    {
        dim3 g(C_DIM / 32, C_DIM / 32);
        k_transpose_split<<<g, dim3(32, 8)>>>(w_proj, (__nv_bfloat16*)p_wpth,
                                              (__nv_bfloat16*)p_wptl, C_DIM, C_DIM);
    }
    // 3) qkv = x @ w_attn + b_attn  (HMMA)
    {
        dim3 grid(N_QKV / 128, M_ROWS / 128);
        gemm_mma<<<grid, 256, GEMM_SMEM>>>((const __nv_bfloat16*)p_xh,
                                           (const __nv_bfloat16*)p_xl,
                                           (const __nv_bfloat16*)p_wth,
                                           (const __nv_bfloat16*)p_wtl,
                                           b_attn, (float*)p_qkv, N_QKV, C_DIM);
    }
    // 4) causal MHA
    {
        dim3 grid(B_DIM * H_DIM, T_DIM / AT_ROWS);
        flash_attn_kernel<<<grid, AT_ROWS>>>((const float*)p_qkv, (float*)p_att);
    }
    // 5) split att -> bf16 hi/lo
    {
        int n = M_ROWS * C_DIM;
        k_split<<<n / 4 / 256, 256>>>((const float*)p_att, (__nv_bfloat16*)p_ath,
                                      (__nv_bfloat16*)p_atl, n);
    }
    // 6) out = att @ w_proj + b_proj (HMMA)
    {
        dim3 grid(C_DIM / 128, M_ROWS / 128);
        gemm_mma<<<grid, 256, GEMM_SMEM>>>((const __nv_bfloat16*)p_ath,
                                           (const __nv_bfloat16*)p_atl,
                                           (const __nv_bfloat16*)p_wpth,
                                           (const __nv_bfloat16*)p_wptl,
                                           b_proj, out, C_DIM, C_DIM);
    }
}

// round 4
// speedup vs baseline: 2.7627x; 1.9770x over previous
#include <cuda_runtime.h>
#include <cuda_bf16.h>
#include <math_constants.h>
#include <cstdint>

// ---------------------------------------------------------------------------
// Problem constants
// ---------------------------------------------------------------------------
#define B_DIM 4
#define T_DIM 2048
#define C_DIM 1024
#define H_DIM 16
#define D_DIM 64
#define M_ROWS (B_DIM * T_DIM)       // 8192
#define N_QKV  (3 * C_DIM)           // 3072

// ---------------------------------------------------------------------------
// Device scratch (allocation-free rule)
// ---------------------------------------------------------------------------
__device__ float g_qkv[(size_t)M_ROWS * N_QKV];
__device__ float g_att[(size_t)M_ROWS * C_DIM];
__device__ __nv_bfloat16 g_qkvh[(size_t)M_ROWS * N_QKV];
__device__ __nv_bfloat16 g_qkvl[(size_t)M_ROWS * N_QKV];
__device__ __nv_bfloat16 g_xh[(size_t)M_ROWS * C_DIM];
__device__ __nv_bfloat16 g_xl[(size_t)M_ROWS * C_DIM];
__device__ __nv_bfloat16 g_wth[(size_t)N_QKV * C_DIM];   // w_attn^T [3072][1024]
__device__ __nv_bfloat16 g_wtl[(size_t)N_QKV * C_DIM];
__device__ __nv_bfloat16 g_wpth[(size_t)C_DIM * C_DIM];  // w_proj^T [1024][1024]
__device__ __nv_bfloat16 g_wptl[(size_t)C_DIM * C_DIM];
__device__ __nv_bfloat16 g_ath[(size_t)M_ROWS * C_DIM];
__device__ __nv_bfloat16 g_atl[(size_t)M_ROWS * C_DIM];

// ---------------------------------------------------------------------------
// Helpers
// ---------------------------------------------------------------------------
__device__ __forceinline__ uint32_t smem_u32(const void* p) {
    uint32_t a;
    asm("{ .reg .u64 t; cvta.to.shared.u64 t, %1; cvt.u32.u64 %0, t; }"
        : "=r"(a) : "l"(p));
    return a;
}

__device__ __forceinline__ void cp16(uint32_t dst, const void* src) {
    asm volatile("cp.async.cg.shared.global [%0], [%1], 16;"
                 :: "r"(dst), "l"(src));
}
#define CP_COMMIT() asm volatile("cp.async.commit_group;" ::: "memory")
#define CP_WAIT(n)  asm volatile("cp.async.wait_group %0;" :: "n"(n) : "memory")

__device__ __forceinline__ void ldsm4(uint32_t* r, uint32_t addr) {
    asm volatile("ldmatrix.sync.aligned.m8n8.x4.shared.b16 {%0,%1,%2,%3}, [%4];"
                 : "=r"(r[0]), "=r"(r[1]), "=r"(r[2]), "=r"(r[3]) : "r"(addr));
}

__device__ __forceinline__ void ldsm4t(uint32_t* r, uint32_t addr) {
    asm volatile("ldmatrix.sync.aligned.m8n8.x4.trans.shared.b16 {%0,%1,%2,%3}, [%4];"
                 : "=r"(r[0]), "=r"(r[1]), "=r"(r[2]), "=r"(r[3]) : "r"(addr));
}

__device__ __forceinline__ void mma16816(float* c, const uint32_t* a,
                                         const uint32_t* b) {
    asm volatile(
        "mma.sync.aligned.m16n8k16.row.col.f32.bf16.bf16.f32 "
        "{%0,%1,%2,%3}, {%4,%5,%6,%7}, {%8,%9}, {%0,%1,%2,%3};"
        : "+f"(c[0]), "+f"(c[1]), "+f"(c[2]), "+f"(c[3])
        : "r"(a[0]), "r"(a[1]), "r"(a[2]), "r"(a[3]), "r"(b[0]), "r"(b[1]));
}

// Fast exp on the FMA pipe (no MUFU). Valid for x <= 0; err ~3e-6 rel.
__device__ __forceinline__ float fexp(float x) {
    const float LOG2E = 1.4426950408889634f;
    const float MAGIC = 12582912.0f;          // 1.5 * 2^23
    x = fmaxf(x, -80.0f);
    float t = fmaf(x, LOG2E, MAGIC);
    int   i = __float_as_int(t);
    float n = t - MAGIC;
    float f = fmaf(x, LOG2E, -n);             // f in [-0.5, 0.5]
    float p = 0.0013333558f;
    p = fmaf(p, f, 0.0096181291f);
    p = fmaf(p, f, 0.0555041086f);
    p = fmaf(p, f, 0.2402265069f);
    p = fmaf(p, f, 0.6931471806f);
    p = fmaf(p, f, 1.0f);
    return __int_as_float(__float_as_int(p) + (i << 23));
}

// Split a pair of floats into packed bf16 hi / lo uint32 fragments
__device__ __forceinline__ void split2(float x, float y, uint32_t& h, uint32_t& l) {
    __nv_bfloat16 hx = __float2bfloat16(x);
    __nv_bfloat16 hy = __float2bfloat16(y);
    __nv_bfloat16 lx = __float2bfloat16(x - __bfloat162float(hx));
    __nv_bfloat16 ly = __float2bfloat16(y - __bfloat162float(hy));
    __nv_bfloat162 hp(hx, hy), lp(lx, ly);
    h = *reinterpret_cast<uint32_t*>(&hp);
    l = *reinterpret_cast<uint32_t*>(&lp);
}

// ---------------------------------------------------------------------------
// Prep kernels
// ---------------------------------------------------------------------------
__global__ void k_split(const float* __restrict__ in,
                        __nv_bfloat16* __restrict__ hi,
                        __nv_bfloat16* __restrict__ lo, int n)
{
    int i = (blockIdx.x * blockDim.x + threadIdx.x) * 4;
    if (i >= n) return;
    float4 v = *(const float4*)(in + i);
    float f[4] = {v.x, v.y, v.z, v.w};
    __nv_bfloat16 h[4], l[4];
#pragma unroll
    for (int j = 0; j < 4; ++j) {
        h[j] = __float2bfloat16(f[j]);
        l[j] = __float2bfloat16(f[j] - __bfloat162float(h[j]));
    }
    *(__nv_bfloat162*)(hi + i)     = __nv_bfloat162(h[0], h[1]);
    *(__nv_bfloat162*)(hi + i + 2) = __nv_bfloat162(h[2], h[3]);
    *(__nv_bfloat162*)(lo + i)     = __nv_bfloat162(l[0], l[1]);
    *(__nv_bfloat162*)(lo + i + 2) = __nv_bfloat162(l[2], l[3]);
}

// W[K][N] row-major -> T[N][K] bf16 hi/lo
__global__ void k_transpose_split(const float* __restrict__ W,
                                  __nv_bfloat16* __restrict__ Th,
                                  __nv_bfloat16* __restrict__ Tl,
                                  int K, int N)
{
    __shared__ float tile[32][33];
    const int k0 = blockIdx.y * 32;
    const int n0 = blockIdx.x * 32;
    const int tx = threadIdx.x;
    const int ty = threadIdx.y;
#pragma unroll
    for (int r = 0; r < 4; ++r)
        tile[ty + r * 8][tx] = W[(size_t)(k0 + ty + r * 8) * N + n0 + tx];
    __syncthreads();
#pragma unroll
    for (int r = 0; r < 4; ++r) {
        float v = tile[tx][ty + r * 8];
        __nv_bfloat16 h = __float2bfloat16(v);
        __nv_bfloat16 l = __float2bfloat16(v - __bfloat162float(h));
        size_t o = (size_t)(n0 + ty + r * 8) * K + k0 + tx;
        Th[o] = h;
        Tl[o] = l;
    }
}

// ---------------------------------------------------------------------------
// HMMA GEMM (unchanged from round 3): C = A @ Bt^T + bias, hi/lo 3-product
// ---------------------------------------------------------------------------
#define BK 32
#define LDSS 40
#define TILE_B (128 * LDSS * 2)
#define STAGE_B (4 * TILE_B)
#define GEMM_SMEM (2 * STAGE_B)

__global__ void __launch_bounds__(256, 1)
gemm_mma(const __nv_bfloat16* __restrict__ Ah, const __nv_bfloat16* __restrict__ Al,
         const __nv_bfloat16* __restrict__ Bh, const __nv_bfloat16* __restrict__ Bl,
         const float* __restrict__ bias, float* __restrict__ C, int N, int K)
{
    extern __shared__ __nv_bfloat16 sm[];
    const uint32_t sbase = smem_u32(sm);

    const int tid  = threadIdx.x;
    const int lane = tid & 31;
    const int wid  = tid >> 5;
    const int m0 = blockIdx.y * 128;
    const int n0 = blockIdx.x * 128;
    const int wm = (wid & 1) * 64;
    const int wn = (wid >> 1) * 32;

    float acc[4][4][4];
#pragma unroll
    for (int i = 0; i < 4; ++i)
#pragma unroll
        for (int j = 0; j < 4; ++j)
#pragma unroll
            for (int k = 0; k < 4; ++k) acc[i][j][k] = 0.0f;

    const int r0 = tid >> 2, s0 = (tid & 3);
    const int r1 = (tid + 256) >> 2, s1 = (tid & 3);

    const __nv_bfloat16* a0h = Ah + (size_t)(m0 + r0) * K + s0 * 8;
    const __nv_bfloat16* a0l = Al + (size_t)(m0 + r0) * K + s0 * 8;
    const __nv_bfloat16* b0h = Bh + (size_t)(n0 + r0) * K + s0 * 8;
    const __nv_bfloat16* b0l = Bl + (size_t)(n0 + r0) * K + s0 * 8;
    const __nv_bfloat16* a1h = Ah + (size_t)(m0 + r1) * K + s1 * 8;
    const __nv_bfloat16* a1l = Al + (size_t)(m0 + r1) * K + s1 * 8;
    const __nv_bfloat16* b1h = Bh + (size_t)(n0 + r1) * K + s1 * 8;
    const __nv_bfloat16* b1l = Bl + (size_t)(n0 + r1) * K + s1 * 8;
    const uint32_t d0 = (uint32_t)r0 * (LDSS * 2) + (uint32_t)s0 * 16;
    const uint32_t d1 = (uint32_t)r1 * (LDSS * 2) + (uint32_t)s1 * 16;

    auto load_chunk = [&](int c, int buf) {
        const int koff = c * BK;
        const uint32_t db = sbase + buf * STAGE_B;
        cp16(db + 0 * TILE_B + d0, a0h + koff);
        cp16(db + 1 * TILE_B + d0, a0l + koff);
        cp16(db + 2 * TILE_B + d0, b0h + koff);
        cp16(db + 3 * TILE_B + d0, b0l + koff);
        cp16(db + 0 * TILE_B + d1, a1h + koff);
        cp16(db + 1 * TILE_B + d1, a1l + koff);
        cp16(db + 2 * TILE_B + d1, b1h + koff);
        cp16(db + 3 * TILE_B + d1, b1l + koff);
        CP_COMMIT();
    };

    const int NC = K / BK;
    load_chunk(0, 0);

    for (int c = 0; c < NC; ++c) {
        const int buf = c & 1;
        if (c + 1 < NC) {
            load_chunk(c + 1, buf ^ 1);
            CP_WAIT(1);
        } else {
            CP_WAIT(0);
        }
        __syncthreads();

        const uint32_t tb = sbase + buf * STAGE_B;
#pragma unroll
        for (int ks = 0; ks < 2; ++ks) {
            uint32_t ah[4][4], al[4][4], bh[2][4], bl[2][4];
#pragma unroll
            for (int mi = 0; mi < 4; ++mi) {
                uint32_t off = (uint32_t)(wm + mi * 16 + (lane & 15)) * (LDSS * 2)
                             + ks * 32 + (lane >> 4) * 16;
                ldsm4(ah[mi], tb + 0 * TILE_B + off);
                ldsm4(al[mi], tb + 1 * TILE_B + off);
            }
#pragma unroll
            for (int np = 0; np < 2; ++np) {
                uint32_t off = (uint32_t)(wn + np * 16 + (lane & 7)
                             + ((lane >> 4) & 1) * 8) * (LDSS * 2)
                             + ks * 32 + ((lane >> 3) & 1) * 16;
                ldsm4(bh[np], tb + 2 * TILE_B + off);
                ldsm4(bl[np], tb + 3 * TILE_B + off);
            }
#pragma unroll
            for (int mi = 0; mi < 4; ++mi)
#pragma unroll
                for (int ni = 0; ni < 4; ++ni) {
                    const uint32_t* fh = &bh[ni >> 1][(ni & 1) * 2];
                    const uint32_t* fl = &bl[ni >> 1][(ni & 1) * 2];
                    mma16816(acc[mi][ni], ah[mi], fh);
                    mma16816(acc[mi][ni], ah[mi], fl);
                    mma16816(acc[mi][ni], al[mi], fh);
                }
        }
        __syncthreads();
    }

#pragma unroll
    for (int mi = 0; mi < 4; ++mi) {
        const int row = m0 + wm + mi * 16 + (lane >> 2);
#pragma unroll
        for (int ni = 0; ni < 4; ++ni) {
            const int col = n0 + wn + ni * 8 + (lane & 3) * 2;
            const float b0v = bias[col];
            const float b1v = bias[col + 1];
            float2 v0, v1;
            v0.x = acc[mi][ni][0] + b0v;
            v0.y = acc[mi][ni][1] + b1v;
            v1.x = acc[mi][ni][2] + b0v;
            v1.y = acc[mi][ni][3] + b1v;
            *(float2*)(C + (size_t)row * N + col)       = v0;
            *(float2*)(C + (size_t)(row + 8) * N + col) = v1;
        }
    }
}

// ---------------------------------------------------------------------------
// HMMA causal flash attention. CTA: 128 q-rows x one (b,h). 8 warps x 16 rows.
// K-tile = 64 keys. bf16 hi/lo 3-product for S=QK^T and O=PV. fp32 softmax.
// ---------------------------------------------------------------------------
#define FA_BQ   128
#define FA_BC   64
#define FA_LDB  144                   // smem row stride bytes (72 bf16, padded)
#define FA_QH   0
#define FA_QL   (FA_BQ * FA_LDB)      // 18432
#define FA_BUF  (2 * FA_BQ * FA_LDB)  // 36864
#define FA_TILE (FA_BC * FA_LDB)      // 9216
#define FA_BUFSZ (4 * FA_TILE)        // 36864 (Kh,Kl,Vh,Vl)
#define FA_SMEM (FA_BUF + 2 * FA_BUFSZ)  // 110592
#define NEG_BIG (-1e30f)

__global__ void __launch_bounds__(256, 1)
flash_mma(const __nv_bfloat16* __restrict__ qh,
          const __nv_bfloat16* __restrict__ ql,
          float* __restrict__ out)
{
    extern __shared__ char fsm[];
    const uint32_t sb = smem_u32(fsm);

    const int tid  = threadIdx.x;
    const int lane = tid & 31;
    const int wid  = tid >> 5;
    const int b = blockIdx.x >> 4;
    const int h = blockIdx.x & 15;
    const int yy = (int)gridDim.y - 1 - (int)blockIdx.y;   // heavy tiles first
    const int q0 = yy * FA_BQ;
    const int NT = 2 * (yy + 1);
    const int bT = b * T_DIM;
    const int hoff = h * D_DIM;

    // ---- load Q tile (hi/lo) into smem ----
#pragma unroll
    for (int i = 0; i < 8; ++i) {
        int idx = tid + i * 256;          // 0..2047
        int arr = idx >> 10;              // 0 = hi, 1 = lo
        int wi  = idx & 1023;
        int row = wi >> 3;
        int ch  = wi & 7;
        const __nv_bfloat16* src = (arr ? ql : qh)
            + (size_t)(bT + q0 + row) * N_QKV + hoff + ch * 8;
        cp16(sb + arr * (FA_BQ * FA_LDB) + row * FA_LDB + ch * 16, src);
    }
    CP_COMMIT();
    CP_WAIT(0);
    __syncthreads();

    // ---- Q fragments to registers ----
    uint32_t qfh[4][4], qfl[4][4];
#pragma unroll
    for (int ks = 0; ks < 4; ++ks) {
        uint32_t off = (uint32_t)(wid * 16 + (lane & 15)) * FA_LDB
                     + ks * 32 + (lane >> 4) * 16;
        ldsm4(qfh[ks], sb + FA_QH + off);
        ldsm4(qfl[ks], sb + FA_QL + off);
    }
    __syncthreads();

    // ---- state ----
    float o[8][4];
#pragma unroll
    for (int i = 0; i < 8; ++i)
#pragma unroll
        for (int j = 0; j < 4; ++j) o[i][j] = 0.0f;
    float m0 = NEG_BIG, m1 = NEG_BIG, l0 = 0.0f, l1 = 0.0f;
    const int qr  = q0 + wid * 16;
    const int qp0 = qr + (lane >> 2);
    const int qp1 = qp0 + 8;

    auto load_tile = [&](int t, int buf) {
        const int k0 = t * FA_BC;
        const int row = tid >> 2;
        const int ch2 = (tid & 3) * 2;
        const size_t rb = (size_t)(bT + k0 + row) * N_QKV + hoff;
        const uint32_t tb = sb + FA_BUF + buf * FA_BUFSZ;
        const uint32_t d = tb + row * FA_LDB + ch2 * 16;
        const __nv_bfloat16* skh = qh + rb + C_DIM;
        const __nv_bfloat16* skl = ql + rb + C_DIM;
        const __nv_bfloat16* svh = qh + rb + 2 * C_DIM;
        const __nv_bfloat16* svl = ql + rb + 2 * C_DIM;
        cp16(d + 0 * FA_TILE,      skh + ch2 * 8);
        cp16(d + 0 * FA_TILE + 16, skh + ch2 * 8 + 8);
        cp16(d + 1 * FA_TILE,      skl + ch2 * 8);
        cp16(d + 1 * FA_TILE + 16, skl + ch2 * 8 + 8);
        cp16(d + 2 * FA_TILE,      svh + ch2 * 8);
        cp16(d + 2 * FA_TILE + 16, svh + ch2 * 8 + 8);
        cp16(d + 3 * FA_TILE,      svl + ch2 * 8);
        cp16(d + 3 * FA_TILE + 16, svl + ch2 * 8 + 8);
        CP_COMMIT();
    };

    load_tile(0, 0);

    for (int t = 0; t < NT; ++t) {
        const int buf = t & 1;
        if (t + 1 < NT) {
            load_tile(t + 1, buf ^ 1);
            CP_WAIT(1);
        } else {
            CP_WAIT(0);
        }
        __syncthreads();

        const int k0 = t * FA_BC;
        if (k0 <= qr + 15) {               // warp has unmasked work
            const uint32_t tb = sb + FA_BUF + buf * FA_BUFSZ;

            // ---- scores S = Q K^T (3-product split) ----
            float s[8][4];
#pragma unroll
            for (int i = 0; i < 8; ++i)
#pragma unroll
                for (int j = 0; j < 4; ++j) s[i][j] = 0.0f;

#pragma unroll
            for (int ks = 0; ks < 4; ++ks) {
                uint32_t kh[4][4], kl[4][4];
#pragma unroll
                for (int np = 0; np < 4; ++np) {
                    uint32_t off = (uint32_t)(np * 16 + (lane & 7)
                                 + ((lane >> 4) & 1) * 8) * FA_LDB
                                 + ks * 32 + ((lane >> 3) & 1) * 16;
                    ldsm4(kh[np], tb + 0 * FA_TILE + off);
                    ldsm4(kl[np], tb + 1 * FA_TILE + off);
                }
#pragma unroll
                for (int ni = 0; ni < 8; ++ni) {
                    const uint32_t* fh = &kh[ni >> 1][(ni & 1) * 2];
                    const uint32_t* fl = &kl[ni >> 1][(ni & 1) * 2];
                    mma16816(s[ni], qfh[ks], fh);
                    mma16816(s[ni], qfh[ks], fl);
                    mma16816(s[ni], qfl[ks], fh);
                }
            }

            // ---- scale + causal mask ----
            const bool needm = (k0 + FA_BC - 1 > qr);
#pragma unroll
            for (int ni = 0; ni < 8; ++ni) {
                s[ni][0] *= 0.125f; s[ni][1] *= 0.125f;
                s[ni][2] *= 0.125f; s[ni][3] *= 0.125f;
                if (needm) {
                    int kp = k0 + ni * 8 + 2 * (lane & 3);
                    if (kp     > qp0) s[ni][0] = NEG_BIG;
                    if (kp + 1 > qp0) s[ni][1] = NEG_BIG;
                    if (kp     > qp1) s[ni][2] = NEG_BIG;
                    if (kp + 1 > qp1) s[ni][3] = NEG_BIG;
                }
            }

            // ---- online softmax ----
            float mx0 = NEG_BIG, mx1 = NEG_BIG;
#pragma unroll
            for (int ni = 0; ni < 8; ++ni) {
                mx0 = fmaxf(mx0, fmaxf(s[ni][0], s[ni][1]));
                mx1 = fmaxf(mx1, fmaxf(s[ni][2], s[ni][3]));
            }
            mx0 = fmaxf(mx0, __shfl_xor_sync(0xffffffffu, mx0, 1));
            mx0 = fmaxf(mx0, __shfl_xor_sync(0xffffffffu, mx0, 2));
            mx1 = fmaxf(mx1, __shfl_xor_sync(0xffffffffu, mx1, 1));
            mx1 = fmaxf(mx1, __shfl_xor_sync(0xffffffffu, mx1, 2));
            const float m0n = fmaxf(m0, mx0);
            const float m1n = fmaxf(m1, mx1);
            const float c0 = fexp(m0 - m0n);
            const float c1 = fexp(m1 - m1n);
            l0 *= c0; l1 *= c1;
#pragma unroll
            for (int ni = 0; ni < 8; ++ni) {
                o[ni][0] *= c0; o[ni][1] *= c0;
                o[ni][2] *= c1; o[ni][3] *= c1;
            }
            m0 = m0n; m1 = m1n;

#pragma unroll
            for (int ni = 0; ni < 8; ++ni) {
                s[ni][0] = fexp(s[ni][0] - m0);
                s[ni][1] = fexp(s[ni][1] - m0);
                s[ni][2] = fexp(s[ni][2] - m1);
                s[ni][3] = fexp(s[ni][3] - m1);
                l0 += s[ni][0] + s[ni][1];
                l1 += s[ni][2] + s[ni][3];
            }

            // ---- O += P V (3-product split) ----
#pragma unroll
            for (int ks = 0; ks < 4; ++ks) {
                uint32_t pah[4], pal[4];
                split2(s[2*ks][0],   s[2*ks][1],   pah[0], pal[0]);
                split2(s[2*ks][2],   s[2*ks][3],   pah[1], pal[1]);
                split2(s[2*ks+1][0], s[2*ks+1][1], pah[2], pal[2]);
                split2(s[2*ks+1][2], s[2*ks+1][3], pah[3], pal[3]);

                uint32_t vh[4][4], vl[4][4];
#pragma unroll
                for (int nd = 0; nd < 4; ++nd) {
                    uint32_t off = (uint32_t)(ks * 16 + (lane & 15)) * FA_LDB
                                 + nd * 32 + (lane >> 4) * 16;
                    ldsm4t(vh[nd], tb + 2 * FA_TILE + off);
                    ldsm4t(vl[nd], tb + 3 * FA_TILE + off);
                }
#pragma unroll
                for (int ni = 0; ni < 8; ++ni) {
                    const uint32_t* fh = &vh[ni >> 1][(ni & 1) * 2];
                    const uint32_t* fl = &vl[ni >> 1][(ni & 1) * 2];
                    mma16816(o[ni], pah, fh);
                    mma16816(o[ni], pah, fl);
                    mma16816(o[ni], pal, fh);
                }
            }
        }
        __syncthreads();
    }

    // ---- epilogue: l reduction + store ----
    float L0 = l0 + __shfl_xor_sync(0xffffffffu, l0, 1);
    L0 += __shfl_xor_sync(0xffffffffu, L0, 2);
    float L1 = l1 + __shfl_xor_sync(0xffffffffu, l1, 1);
    L1 += __shfl_xor_sync(0xffffffffu, L1, 2);
    const float i0 = 1.0f / L0;
    const float i1 = 1.0f / L1;

    float* o0 = out + (size_t)(bT + qp0) * C_DIM + hoff + 2 * (lane & 3);
    float* o1 = out + (size_t)(bT + qp1) * C_DIM + hoff + 2 * (lane & 3);
#pragma unroll
    for (int ni = 0; ni < 8; ++ni) {
        float2 v0, v1;
        v0.x = o[ni][0] * i0; v0.y = o[ni][1] * i0;
        v1.x = o[ni][2] * i1; v1.y = o[ni][3] * i1;
        *(float2*)(o0 + ni * 8) = v0;
        *(float2*)(o1 + ni * 8) = v1;
    }
}

// ---------------------------------------------------------------------------
// Launch
// ---------------------------------------------------------------------------
extern "C" void kernel_launch(void* const* d_in, const int* in_sizes, int n_in,
                              void* d_out, int out_size)
{
    const float* x      = (const float*)d_in[0];
    const float* w_attn = (const float*)d_in[1];
    const float* b_attn = (const float*)d_in[2];
    const float* w_proj = (const float*)d_in[3];
    const float* b_proj = (const float*)d_in[4];
    float* out = (float*)d_out;

    void *p_qkv, *p_att, *p_qh, *p_ql, *p_xh, *p_xl, *p_wth, *p_wtl,
         *p_wpth, *p_wptl, *p_ath, *p_atl;
    cudaGetSymbolAddress(&p_qkv,  g_qkv);
    cudaGetSymbolAddress(&p_att,  g_att);
    cudaGetSymbolAddress(&p_qh,   g_qkvh);
    cudaGetSymbolAddress(&p_ql,   g_qkvl);
    cudaGetSymbolAddress(&p_xh,   g_xh);
    cudaGetSymbolAddress(&p_xl,   g_xl);
    cudaGetSymbolAddress(&p_wth,  g_wth);
    cudaGetSymbolAddress(&p_wtl,  g_wtl);
    cudaGetSymbolAddress(&p_wpth, g_wpth);
    cudaGetSymbolAddress(&p_wptl, g_wptl);
    cudaGetSymbolAddress(&p_ath,  g_ath);
    cudaGetSymbolAddress(&p_atl,  g_atl);

    static bool attr_done = false;
    if (!attr_done) {
        cudaFuncSetAttribute(gemm_mma, cudaFuncAttributeMaxDynamicSharedMemorySize,
                             GEMM_SMEM);
        cudaFuncSetAttribute(flash_mma, cudaFuncAttributeMaxDynamicSharedMemorySize,
                             FA_SMEM);
        attr_done = true;
    }

    // 1) split x -> bf16 hi/lo
    {
        int n = M_ROWS * C_DIM;
        k_split<<<n / 4 / 256, 256>>>(x, (__nv_bfloat16*)p_xh, (__nv_bfloat16*)p_xl, n);
    }
    // 2) transpose + split weights
    {
        dim3 g(N_QKV / 32, C_DIM / 32);
        k_transpose_split<<<g, dim3(32, 8)>>>(w_attn, (__nv_bfloat16*)p_wth,
                                              (__nv_bfloat16*)p_wtl, C_DIM, N_QKV);
    }
    {
        dim3 g(C_DIM / 32, C_DIM / 32);
        k_transpose_split<<<g, dim3(32, 8)>>>(w_proj, (__nv_bfloat16*)p_wpth,
                                              (__nv_bfloat16*)p_wptl, C_DIM, C_DIM);
    }
    // 3) qkv = x @ w_attn + b_attn  (HMMA)
    {
        dim3 grid(N_QKV / 128, M_ROWS / 128);
        gemm_mma<<<grid, 256, GEMM_SMEM>>>((const __nv_bfloat16*)p_xh,
                                           (const __nv_bfloat16*)p_xl,
                                           (const __nv_bfloat16*)p_wth,
                                           (const __nv_bfloat16*)p_wtl,
                                           b_attn, (float*)p_qkv, N_QKV, C_DIM);
    }
    // 4) split qkv -> bf16 hi/lo
    {
        int n = M_ROWS * N_QKV;
        k_split<<<n / 4 / 256, 256>>>((const float*)p_qkv,
                                      (__nv_bfloat16*)p_qh, (__nv_bfloat16*)p_ql, n);
    }
    // 5) causal MHA (HMMA flash)
    {
        dim3 grid(B_DIM * H_DIM, T_DIM / FA_BQ);
        flash_mma<<<grid, 256, FA_SMEM>>>((const __nv_bfloat16*)p_qh,
                                          (const __nv_bfloat16*)p_ql,
                                          (float*)p_att);
    }
    // 6) split att -> bf16 hi/lo
    {
        int n = M_ROWS * C_DIM;
        k_split<<<n / 4 / 256, 256>>>((const float*)p_att, (__nv_bfloat16*)p_ath,
                                      (__nv_bfloat16*)p_atl, n);
    }
    // 7) out = att @ w_proj + b_proj (HMMA)
    {
        dim3 grid(C_DIM / 128, M_ROWS / 128);
        gemm_mma<<<grid, 256, GEMM_SMEM>>>((const __nv_bfloat16*)p_ath,
                                           (const __nv_bfloat16*)p_atl,
                                           (const __nv_bfloat16*)p_wpth,
                                           (const __nv_bfloat16*)p_wptl,
                                           b_proj, out, C_DIM, C_DIM);
    }
}

// round 5
// speedup vs baseline: 3.1024x; 1.1229x over previous
#include <cuda_runtime.h>
#include <cuda_bf16.h>
#include <math_constants.h>
#include <cstdint>

// ---------------------------------------------------------------------------
// Problem constants
// ---------------------------------------------------------------------------
#define B_DIM 4
#define T_DIM 2048
#define C_DIM 1024
#define H_DIM 16
#define D_DIM 64
#define M_ROWS (B_DIM * T_DIM)       // 8192
#define N_QKV  (3 * C_DIM)           // 3072

// ---------------------------------------------------------------------------
// Device scratch (allocation-free rule)
// ---------------------------------------------------------------------------
__device__ __nv_bfloat16 g_qkvh[(size_t)M_ROWS * N_QKV];
__device__ __nv_bfloat16 g_qkvl[(size_t)M_ROWS * N_QKV];
__device__ __nv_bfloat16 g_xh[(size_t)M_ROWS * C_DIM];
__device__ __nv_bfloat16 g_xl[(size_t)M_ROWS * C_DIM];
__device__ __nv_bfloat16 g_wth[(size_t)N_QKV * C_DIM];   // w_attn^T [3072][1024]
__device__ __nv_bfloat16 g_wtl[(size_t)N_QKV * C_DIM];
__device__ __nv_bfloat16 g_wpth[(size_t)C_DIM * C_DIM];  // w_proj^T [1024][1024]
__device__ __nv_bfloat16 g_wptl[(size_t)C_DIM * C_DIM];
__device__ __nv_bfloat16 g_ath[(size_t)M_ROWS * C_DIM];
__device__ __nv_bfloat16 g_atl[(size_t)M_ROWS * C_DIM];

// ---------------------------------------------------------------------------
// Helpers
// ---------------------------------------------------------------------------
__device__ __forceinline__ uint32_t smem_u32(const void* p) {
    uint32_t a;
    asm("{ .reg .u64 t; cvta.to.shared.u64 t, %1; cvt.u32.u64 %0, t; }"
        : "=r"(a) : "l"(p));
    return a;
}

__device__ __forceinline__ void cp16(uint32_t dst, const void* src) {
    asm volatile("cp.async.cg.shared.global [%0], [%1], 16;"
                 :: "r"(dst), "l"(src));
}
#define CP_COMMIT() asm volatile("cp.async.commit_group;" ::: "memory")
#define CP_WAIT(n)  asm volatile("cp.async.wait_group %0;" :: "n"(n) : "memory")

__device__ __forceinline__ void ldsm4(uint32_t* r, uint32_t addr) {
    asm volatile("ldmatrix.sync.aligned.m8n8.x4.shared.b16 {%0,%1,%2,%3}, [%4];"
                 : "=r"(r[0]), "=r"(r[1]), "=r"(r[2]), "=r"(r[3]) : "r"(addr));
}

__device__ __forceinline__ void ldsm4t(uint32_t* r, uint32_t addr) {
    asm volatile("ldmatrix.sync.aligned.m8n8.x4.trans.shared.b16 {%0,%1,%2,%3}, [%4];"
                 : "=r"(r[0]), "=r"(r[1]), "=r"(r[2]), "=r"(r[3]) : "r"(addr));
}

__device__ __forceinline__ void mma16816(float* c, const uint32_t* a,
                                         const uint32_t* b) {
    asm volatile(
        "mma.sync.aligned.m16n8k16.row.col.f32.bf16.bf16.f32 "
        "{%0,%1,%2,%3}, {%4,%5,%6,%7}, {%8,%9}, {%0,%1,%2,%3};"
        : "+f"(c[0]), "+f"(c[1]), "+f"(c[2]), "+f"(c[3])
        : "r"(a[0]), "r"(a[1]), "r"(a[2]), "r"(a[3]), "r"(b[0]), "r"(b[1]));
}

// Fast exp on the FMA pipe (no MUFU). Valid for x <= 0; err ~3e-6 rel.
__device__ __forceinline__ float fexp(float x) {
    const float LOG2E = 1.4426950408889634f;
    const float MAGIC = 12582912.0f;          // 1.5 * 2^23
    x = fmaxf(x, -80.0f);
    float t = fmaf(x, LOG2E, MAGIC);
    int   i = __float_as_int(t);
    float n = t - MAGIC;
    float f = fmaf(x, LOG2E, -n);             // f in [-0.5, 0.5]
    float p = 0.0013333558f;
    p = fmaf(p, f, 0.0096181291f);
    p = fmaf(p, f, 0.0555041086f);
    p = fmaf(p, f, 0.2402265069f);
    p = fmaf(p, f, 0.6931471806f);
    p = fmaf(p, f, 1.0f);
    return __int_as_float(__float_as_int(p) + (i << 23));
}

// Split a pair of floats into packed bf16 hi / lo uint32 fragments
__device__ __forceinline__ void split2(float x, float y, uint32_t& h, uint32_t& l) {
    __nv_bfloat16 hx = __float2bfloat16(x);
    __nv_bfloat16 hy = __float2bfloat16(y);
    __nv_bfloat16 lx = __float2bfloat16(x - __bfloat162float(hx));
    __nv_bfloat16 ly = __float2bfloat16(y - __bfloat162float(hy));
    __nv_bfloat162 hp(hx, hy), lp(lx, ly);
    h = *reinterpret_cast<uint32_t*>(&hp);
    l = *reinterpret_cast<uint32_t*>(&lp);
}

// ---------------------------------------------------------------------------
// Prep kernels
// ---------------------------------------------------------------------------
__global__ void k_split(const float* __restrict__ in,
                        __nv_bfloat16* __restrict__ hi,
                        __nv_bfloat16* __restrict__ lo, int n)
{
    int i = (blockIdx.x * blockDim.x + threadIdx.x) * 4;
    if (i >= n) return;
    float4 v = *(const float4*)(in + i);
    float f[4] = {v.x, v.y, v.z, v.w};
    __nv_bfloat16 h[4], l[4];
#pragma unroll
    for (int j = 0; j < 4; ++j) {
        h[j] = __float2bfloat16(f[j]);
        l[j] = __float2bfloat16(f[j] - __bfloat162float(h[j]));
    }
    *(__nv_bfloat162*)(hi + i)     = __nv_bfloat162(h[0], h[1]);
    *(__nv_bfloat162*)(hi + i + 2) = __nv_bfloat162(h[2], h[3]);
    *(__nv_bfloat162*)(lo + i)     = __nv_bfloat162(l[0], l[1]);
    *(__nv_bfloat162*)(lo + i + 2) = __nv_bfloat162(l[2], l[3]);
}

// W[K][N] row-major -> T[N][K] bf16 hi/lo
__global__ void k_transpose_split(const float* __restrict__ W,
                                  __nv_bfloat16* __restrict__ Th,
                                  __nv_bfloat16* __restrict__ Tl,
                                  int K, int N)
{
    __shared__ float tile[32][33];
    const int k0 = blockIdx.y * 32;
    const int n0 = blockIdx.x * 32;
    const int tx = threadIdx.x;
    const int ty = threadIdx.y;
#pragma unroll
    for (int r = 0; r < 4; ++r)
        tile[ty + r * 8][tx] = W[(size_t)(k0 + ty + r * 8) * N + n0 + tx];
    __syncthreads();
#pragma unroll
    for (int r = 0; r < 4; ++r) {
        float v = tile[tx][ty + r * 8];
        __nv_bfloat16 h = __float2bfloat16(v);
        __nv_bfloat16 l = __float2bfloat16(v - __bfloat162float(h));
        size_t o = (size_t)(n0 + ty + r * 8) * K + k0 + tx;
        Th[o] = h;
        Tl[o] = l;
    }
}

// ---------------------------------------------------------------------------
// HMMA GEMM: C = A @ Bt^T + bias, hi/lo 3-product split.
// 128x128 CTA tile, BK=32, 8 warps, cp.async double buffer, 2 CTAs/SM.
// SPLIT_OUT: write bf16 hi/lo (for qkv); else fp32.
// ---------------------------------------------------------------------------
#define BK 32
#define LDSS 40
#define TILE_B (128 * LDSS * 2)
#define STAGE_B (4 * TILE_B)
#define GEMM_SMEM (2 * STAGE_B)      // 81920 B -> 2 CTAs fit in 228KB

template<bool SPLIT_OUT>
__global__ void __launch_bounds__(256, 2)
gemm_mma(const __nv_bfloat16* __restrict__ Ah, const __nv_bfloat16* __restrict__ Al,
         const __nv_bfloat16* __restrict__ Bh, const __nv_bfloat16* __restrict__ Bl,
         const float* __restrict__ bias, float* __restrict__ C,
         __nv_bfloat16* __restrict__ Ch, __nv_bfloat16* __restrict__ Cl,
         int N, int K)
{
    extern __shared__ __nv_bfloat16 sm[];
    const uint32_t sbase = smem_u32(sm);

    const int tid  = threadIdx.x;
    const int lane = tid & 31;
    const int wid  = tid >> 5;
    const int m0 = blockIdx.y * 128;
    const int n0 = blockIdx.x * 128;
    const int wm = (wid & 1) * 64;
    const int wn = (wid >> 1) * 32;

    float acc[4][4][4];
#pragma unroll
    for (int i = 0; i < 4; ++i)
#pragma unroll
        for (int j = 0; j < 4; ++j)
#pragma unroll
            for (int k = 0; k < 4; ++k) acc[i][j][k] = 0.0f;

    const int r0 = tid >> 2, s0 = (tid & 3);
    const int r1 = (tid + 256) >> 2, s1 = (tid & 3);

    const __nv_bfloat16* a0h = Ah + (size_t)(m0 + r0) * K + s0 * 8;
    const __nv_bfloat16* a0l = Al + (size_t)(m0 + r0) * K + s0 * 8;
    const __nv_bfloat16* b0h = Bh + (size_t)(n0 + r0) * K + s0 * 8;
    const __nv_bfloat16* b0l = Bl + (size_t)(n0 + r0) * K + s0 * 8;
    const __nv_bfloat16* a1h = Ah + (size_t)(m0 + r1) * K + s1 * 8;
    const __nv_bfloat16* a1l = Al + (size_t)(m0 + r1) * K + s1 * 8;
    const __nv_bfloat16* b1h = Bh + (size_t)(n0 + r1) * K + s1 * 8;
    const __nv_bfloat16* b1l = Bl + (size_t)(n0 + r1) * K + s1 * 8;
    const uint32_t d0 = (uint32_t)r0 * (LDSS * 2) + (uint32_t)s0 * 16;
    const uint32_t d1 = (uint32_t)r1 * (LDSS * 2) + (uint32_t)s1 * 16;

    auto load_chunk = [&](int c, int buf) {
        const int koff = c * BK;
        const uint32_t db = sbase + buf * STAGE_B;
        cp16(db + 0 * TILE_B + d0, a0h + koff);
        cp16(db + 1 * TILE_B + d0, a0l + koff);
        cp16(db + 2 * TILE_B + d0, b0h + koff);
        cp16(db + 3 * TILE_B + d0, b0l + koff);
        cp16(db + 0 * TILE_B + d1, a1h + koff);
        cp16(db + 1 * TILE_B + d1, a1l + koff);
        cp16(db + 2 * TILE_B + d1, b1h + koff);
        cp16(db + 3 * TILE_B + d1, b1l + koff);
        CP_COMMIT();
    };

    const int NC = K / BK;
    load_chunk(0, 0);

    for (int c = 0; c < NC; ++c) {
        const int buf = c & 1;
        if (c + 1 < NC) {
            load_chunk(c + 1, buf ^ 1);
            CP_WAIT(1);
        } else {
            CP_WAIT(0);
        }
        __syncthreads();

        const uint32_t tb = sbase + buf * STAGE_B;
#pragma unroll
        for (int ks = 0; ks < 2; ++ks) {
            uint32_t ah[4][4], al[4][4];
#pragma unroll
            for (int mi = 0; mi < 4; ++mi) {
                uint32_t off = (uint32_t)(wm + mi * 16 + (lane & 15)) * (LDSS * 2)
                             + ks * 32 + (lane >> 4) * 16;
                ldsm4(ah[mi], tb + 0 * TILE_B + off);
                ldsm4(al[mi], tb + 1 * TILE_B + off);
            }
            // B fragments loaded per 16-col group to cap live registers
#pragma unroll
            for (int np = 0; np < 2; ++np) {
                uint32_t bh[4], bl[4];
                uint32_t off = (uint32_t)(wn + np * 16 + (lane & 7)
                             + ((lane >> 4) & 1) * 8) * (LDSS * 2)
                             + ks * 32 + ((lane >> 3) & 1) * 16;
                ldsm4(bh, tb + 2 * TILE_B + off);
                ldsm4(bl, tb + 3 * TILE_B + off);
#pragma unroll
                for (int mi = 0; mi < 4; ++mi)
#pragma unroll
                    for (int nj = 0; nj < 2; ++nj) {
                        float* a = acc[mi][2 * np + nj];
                        mma16816(a, ah[mi], &bh[nj * 2]);
                        mma16816(a, ah[mi], &bl[nj * 2]);
                        mma16816(a, al[mi], &bh[nj * 2]);
                    }
            }
        }
        __syncthreads();
    }

#pragma unroll
    for (int mi = 0; mi < 4; ++mi) {
        const int row = m0 + wm + mi * 16 + (lane >> 2);
#pragma unroll
        for (int ni = 0; ni < 4; ++ni) {
            const int col = n0 + wn + ni * 8 + (lane & 3) * 2;
            const float b0v = bias[col];
            const float b1v = bias[col + 1];
            const float v0x = acc[mi][ni][0] + b0v;
            const float v0y = acc[mi][ni][1] + b1v;
            const float v1x = acc[mi][ni][2] + b0v;
            const float v1y = acc[mi][ni][3] + b1v;
            if (SPLIT_OUT) {
                uint32_t h0, l0, h1, l1;
                split2(v0x, v0y, h0, l0);
                split2(v1x, v1y, h1, l1);
                const size_t o0 = (size_t)row * N + col;
                const size_t o1 = (size_t)(row + 8) * N + col;
                *(uint32_t*)(Ch + o0) = h0;
                *(uint32_t*)(Cl + o0) = l0;
                *(uint32_t*)(Ch + o1) = h1;
                *(uint32_t*)(Cl + o1) = l1;
            } else {
                float2 v0, v1;
                v0.x = v0x; v0.y = v0y;
                v1.x = v1x; v1.y = v1y;
                *(float2*)(C + (size_t)row * N + col)       = v0;
                *(float2*)(C + (size_t)(row + 8) * N + col) = v1;
            }
        }
    }
}

// ---------------------------------------------------------------------------
// HMMA causal flash attention. CTA: 128 q-rows x one (b,h). 8 warps x 16 rows.
// Writes output directly as bf16 hi/lo for the proj GEMM.
// ---------------------------------------------------------------------------
#define FA_BQ   128
#define FA_BC   64
#define FA_LDB  144
#define FA_QH   0
#define FA_QL   (FA_BQ * FA_LDB)
#define FA_BUF  (2 * FA_BQ * FA_LDB)
#define FA_TILE (FA_BC * FA_LDB)
#define FA_BUFSZ (4 * FA_TILE)
#define FA_SMEM (FA_BUF + 2 * FA_BUFSZ)  // 110592
#define NEG_BIG (-1e30f)

__global__ void __launch_bounds__(256, 1)
flash_mma(const __nv_bfloat16* __restrict__ qh,
          const __nv_bfloat16* __restrict__ ql,
          __nv_bfloat16* __restrict__ ath,
          __nv_bfloat16* __restrict__ atl)
{
    extern __shared__ char fsm[];
    const uint32_t sb = smem_u32(fsm);

    const int tid  = threadIdx.x;
    const int lane = tid & 31;
    const int wid  = tid >> 5;
    const int b = blockIdx.x >> 4;
    const int h = blockIdx.x & 15;
    const int yy = (int)gridDim.y - 1 - (int)blockIdx.y;   // heavy tiles first
    const int q0 = yy * FA_BQ;
    const int NT = 2 * (yy + 1);
    const int bT = b * T_DIM;
    const int hoff = h * D_DIM;

    // ---- load Q tile (hi/lo) into smem ----
#pragma unroll
    for (int i = 0; i < 8; ++i) {
        int idx = tid + i * 256;
        int arr = idx >> 10;
        int wi  = idx & 1023;
        int row = wi >> 3;
        int ch  = wi & 7;
        const __nv_bfloat16* src = (arr ? ql : qh)
            + (size_t)(bT + q0 + row) * N_QKV + hoff + ch * 8;
        cp16(sb + arr * (FA_BQ * FA_LDB) + row * FA_LDB + ch * 16, src);
    }
    CP_COMMIT();
    CP_WAIT(0);
    __syncthreads();

    uint32_t qfh[4][4], qfl[4][4];
#pragma unroll
    for (int ks = 0; ks < 4; ++ks) {
        uint32_t off = (uint32_t)(wid * 16 + (lane & 15)) * FA_LDB
                     + ks * 32 + (lane >> 4) * 16;
        ldsm4(qfh[ks], sb + FA_QH + off);
        ldsm4(qfl[ks], sb + FA_QL + off);
    }
    __syncthreads();

    float o[8][4];
#pragma unroll
    for (int i = 0; i < 8; ++i)
#pragma unroll
        for (int j = 0; j < 4; ++j) o[i][j] = 0.0f;
    float m0 = NEG_BIG, m1 = NEG_BIG, l0 = 0.0f, l1 = 0.0f;
    const int qr  = q0 + wid * 16;
    const int qp0 = qr + (lane >> 2);
    const int qp1 = qp0 + 8;

    auto load_tile = [&](int t, int buf) {
        const int k0 = t * FA_BC;
        const int row = tid >> 2;
        const int ch2 = (tid & 3) * 2;
        const size_t rb = (size_t)(bT + k0 + row) * N_QKV + hoff;
        const uint32_t tb = sb + FA_BUF + buf * FA_BUFSZ;
        const uint32_t d = tb + row * FA_LDB + ch2 * 16;
        const __nv_bfloat16* skh = qh + rb + C_DIM;
        const __nv_bfloat16* skl = ql + rb + C_DIM;
        const __nv_bfloat16* svh = qh + rb + 2 * C_DIM;
        const __nv_bfloat16* svl = ql + rb + 2 * C_DIM;
        cp16(d + 0 * FA_TILE,      skh + ch2 * 8);
        cp16(d + 0 * FA_TILE + 16, skh + ch2 * 8 + 8);
        cp16(d + 1 * FA_TILE,      skl + ch2 * 8);
        cp16(d + 1 * FA_TILE + 16, skl + ch2 * 8 + 8);
        cp16(d + 2 * FA_TILE,      svh + ch2 * 8);
        cp16(d + 2 * FA_TILE + 16, svh + ch2 * 8 + 8);
        cp16(d + 3 * FA_TILE,      svl + ch2 * 8);
        cp16(d + 3 * FA_TILE + 16, svl + ch2 * 8 + 8);
        CP_COMMIT();
    };

    load_tile(0, 0);

    for (int t = 0; t < NT; ++t) {
        const int buf = t & 1;
        if (t + 1 < NT) {
            load_tile(t + 1, buf ^ 1);
            CP_WAIT(1);
        } else {
            CP_WAIT(0);
        }
        __syncthreads();

        const int k0 = t * FA_BC;
        if (k0 <= qr + 15) {
            const uint32_t tb = sb + FA_BUF + buf * FA_BUFSZ;

            float s[8][4];
#pragma unroll
            for (int i = 0; i < 8; ++i)
#pragma unroll
                for (int j = 0; j < 4; ++j) s[i][j] = 0.0f;

#pragma unroll
            for (int ks = 0; ks < 4; ++ks) {
                uint32_t kh[4][4], kl[4][4];
#pragma unroll
                for (int np = 0; np < 4; ++np) {
                    uint32_t off = (uint32_t)(np * 16 + (lane & 7)
                                 + ((lane >> 4) & 1) * 8) * FA_LDB
                                 + ks * 32 + ((lane >> 3) & 1) * 16;
                    ldsm4(kh[np], tb + 0 * FA_TILE + off);
                    ldsm4(kl[np], tb + 1 * FA_TILE + off);
                }
#pragma unroll
                for (int ni = 0; ni < 8; ++ni) {
                    const uint32_t* fh = &kh[ni >> 1][(ni & 1) * 2];
                    const uint32_t* fl = &kl[ni >> 1][(ni & 1) * 2];
                    mma16816(s[ni], qfh[ks], fh);
                    mma16816(s[ni], qfh[ks], fl);
                    mma16816(s[ni], qfl[ks], fh);
                }
            }

            const bool needm = (k0 + FA_BC - 1 > qr);
#pragma unroll
            for (int ni = 0; ni < 8; ++ni) {
                s[ni][0] *= 0.125f; s[ni][1] *= 0.125f;
                s[ni][2] *= 0.125f; s[ni][3] *= 0.125f;
                if (needm) {
                    int kp = k0 + ni * 8 + 2 * (lane & 3);
                    if (kp     > qp0) s[ni][0] = NEG_BIG;
                    if (kp + 1 > qp0) s[ni][1] = NEG_BIG;
                    if (kp     > qp1) s[ni][2] = NEG_BIG;
                    if (kp + 1 > qp1) s[ni][3] = NEG_BIG;
                }
            }

            float mx0 = NEG_BIG, mx1 = NEG_BIG;
#pragma unroll
            for (int ni = 0; ni < 8; ++ni) {
                mx0 = fmaxf(mx0, fmaxf(s[ni][0], s[ni][1]));
                mx1 = fmaxf(mx1, fmaxf(s[ni][2], s[ni][3]));
            }
            mx0 = fmaxf(mx0, __shfl_xor_sync(0xffffffffu, mx0, 1));
            mx0 = fmaxf(mx0, __shfl_xor_sync(0xffffffffu, mx0, 2));
            mx1 = fmaxf(mx1, __shfl_xor_sync(0xffffffffu, mx1, 1));
            mx1 = fmaxf(mx1, __shfl_xor_sync(0xffffffffu, mx1, 2));
            const float m0n = fmaxf(m0, mx0);
            const float m1n = fmaxf(m1, mx1);
            const float c0 = fexp(m0 - m0n);
            const float c1 = fexp(m1 - m1n);
            l0 *= c0; l1 *= c1;
#pragma unroll
            for (int ni = 0; ni < 8; ++ni) {
                o[ni][0] *= c0; o[ni][1] *= c0;
                o[ni][2] *= c1; o[ni][3] *= c1;
            }
            m0 = m0n; m1 = m1n;

#pragma unroll
            for (int ni = 0; ni < 8; ++ni) {
                s[ni][0] = fexp(s[ni][0] - m0);
                s[ni][1] = fexp(s[ni][1] - m0);
                s[ni][2] = fexp(s[ni][2] - m1);
                s[ni][3] = fexp(s[ni][3] - m1);
                l0 += s[ni][0] + s[ni][1];
                l1 += s[ni][2] + s[ni][3];
            }

#pragma unroll
            for (int ks = 0; ks < 4; ++ks) {
                uint32_t pah[4], pal[4];
                split2(s[2*ks][0],   s[2*ks][1],   pah[0], pal[0]);
                split2(s[2*ks][2],   s[2*ks][3],   pah[1], pal[1]);
                split2(s[2*ks+1][0], s[2*ks+1][1], pah[2], pal[2]);
                split2(s[2*ks+1][2], s[2*ks+1][3], pah[3], pal[3]);

                uint32_t vh[4][4], vl[4][4];
#pragma unroll
                for (int nd = 0; nd < 4; ++nd) {
                    uint32_t off = (uint32_t)(ks * 16 + (lane & 15)) * FA_LDB
                                 + nd * 32 + (lane >> 4) * 16;
                    ldsm4t(vh[nd], tb + 2 * FA_TILE + off);
                    ldsm4t(vl[nd], tb + 3 * FA_TILE + off);
                }
#pragma unroll
                for (int ni = 0; ni < 8; ++ni) {
                    const uint32_t* fh = &vh[ni >> 1][(ni & 1) * 2];
                    const uint32_t* fl = &vl[ni >> 1][(ni & 1) * 2];
                    mma16816(o[ni], pah, fh);
                    mma16816(o[ni], pah, fl);
                    mma16816(o[ni], pal, fh);
                }
            }
        }
        __syncthreads();
    }

    // ---- epilogue: l reduction + split-store bf16 hi/lo ----
    float L0 = l0 + __shfl_xor_sync(0xffffffffu, l0, 1);
    L0 += __shfl_xor_sync(0xffffffffu, L0, 2);
    float L1 = l1 + __shfl_xor_sync(0xffffffffu, l1, 1);
    L1 += __shfl_xor_sync(0xffffffffu, L1, 2);
    const float i0 = 1.0f / L0;
    const float i1 = 1.0f / L1;

    const size_t r0o = (size_t)(bT + qp0) * C_DIM + hoff + 2 * (lane & 3);
    const size_t r1o = (size_t)(bT + qp1) * C_DIM + hoff + 2 * (lane & 3);
#pragma unroll
    for (int ni = 0; ni < 8; ++ni) {
        uint32_t hh, ll;
        split2(o[ni][0] * i0, o[ni][1] * i0, hh, ll);
        *(uint32_t*)(ath + r0o + ni * 8) = hh;
        *(uint32_t*)(atl + r0o + ni * 8) = ll;
        split2(o[ni][2] * i1, o[ni][3] * i1, hh, ll);
        *(uint32_t*)(ath + r1o + ni * 8) = hh;
        *(uint32_t*)(atl + r1o + ni * 8) = ll;
    }
}

// ---------------------------------------------------------------------------
// Launch
// ---------------------------------------------------------------------------
extern "C" void kernel_launch(void* const* d_in, const int* in_sizes, int n_in,
                              void* d_out, int out_size)
{
    const float* x      = (const float*)d_in[0];
    const float* w_attn = (const float*)d_in[1];
    const float* b_attn = (const float*)d_in[2];
    const float* w_proj = (const float*)d_in[3];
    const float* b_proj = (const float*)d_in[4];
    float* out = (float*)d_out;

    void *p_qh, *p_ql, *p_xh, *p_xl, *p_wth, *p_wtl,
         *p_wpth, *p_wptl, *p_ath, *p_atl;
    cudaGetSymbolAddress(&p_qh,   g_qkvh);
    cudaGetSymbolAddress(&p_ql,   g_qkvl);
    cudaGetSymbolAddress(&p_xh,   g_xh);
    cudaGetSymbolAddress(&p_xl,   g_xl);
    cudaGetSymbolAddress(&p_wth,  g_wth);
    cudaGetSymbolAddress(&p_wtl,  g_wtl);
    cudaGetSymbolAddress(&p_wpth, g_wpth);
    cudaGetSymbolAddress(&p_wptl, g_wptl);
    cudaGetSymbolAddress(&p_ath,  g_ath);
    cudaGetSymbolAddress(&p_atl,  g_atl);

    static bool attr_done = false;
    if (!attr_done) {
        cudaFuncSetAttribute(gemm_mma<true>,
                             cudaFuncAttributeMaxDynamicSharedMemorySize, GEMM_SMEM);
        cudaFuncSetAttribute(gemm_mma<false>,
                             cudaFuncAttributeMaxDynamicSharedMemorySize, GEMM_SMEM);
        cudaFuncSetAttribute(flash_mma,
                             cudaFuncAttributeMaxDynamicSharedMemorySize, FA_SMEM);
        attr_done = true;
    }

    // 1) split x -> bf16 hi/lo
    {
        int n = M_ROWS * C_DIM;
        k_split<<<n / 4 / 256, 256>>>(x, (__nv_bfloat16*)p_xh, (__nv_bfloat16*)p_xl, n);
    }
    // 2) transpose + split weights
    {
        dim3 g(N_QKV / 32, C_DIM / 32);
        k_transpose_split<<<g, dim3(32, 8)>>>(w_attn, (__nv_bfloat16*)p_wth,
                                              (__nv_bfloat16*)p_wtl, C_DIM, N_QKV);
    }
    {
        dim3 g(C_DIM / 32, C_DIM / 32);
        k_transpose_split<<<g, dim3(32, 8)>>>(w_proj, (__nv_bfloat16*)p_wpth,
                                              (__nv_bfloat16*)p_wptl, C_DIM, C_DIM);
    }
    // 3) qkv = x @ w_attn + b_attn  (HMMA, direct bf16 hi/lo output)
    {
        dim3 grid(N_QKV / 128, M_ROWS / 128);
        gemm_mma<true><<<grid, 256, GEMM_SMEM>>>(
            (const __nv_bfloat16*)p_xh, (const __nv_bfloat16*)p_xl,
            (const __nv_bfloat16*)p_wth, (const __nv_bfloat16*)p_wtl,
            b_attn, nullptr,
            (__nv_bfloat16*)p_qh, (__nv_bfloat16*)p_ql, N_QKV, C_DIM);
    }
    // 4) causal MHA (HMMA flash, direct bf16 hi/lo output)
    {
        dim3 grid(B_DIM * H_DIM, T_DIM / FA_BQ);
        flash_mma<<<grid, 256, FA_SMEM>>>((const __nv_bfloat16*)p_qh,
                                          (const __nv_bfloat16*)p_ql,
                                          (__nv_bfloat16*)p_ath,
                                          (__nv_bfloat16*)p_atl);
    }
    // 5) out = att @ w_proj + b_proj (HMMA, fp32 output)
    {
        dim3 grid(C_DIM / 128, M_ROWS / 128);
        gemm_mma<false><<<grid, 256, GEMM_SMEM>>>(
            (const __nv_bfloat16*)p_ath, (const __nv_bfloat16*)p_atl,
            (const __nv_bfloat16*)p_wpth, (const __nv_bfloat16*)p_wptl,
            b_proj, out, nullptr, nullptr, C_DIM, C_DIM);
    }
}